// round 14
// baseline (speedup 1.0000x reference)
#include <cuda_runtime.h>
#include <cuda_bf16.h>
#include <math.h>
#include <stdint.h>

// Problem constants (fixed by the reference)
#define NN   50000
#define EE   800000
#define NIN  300
#define HH   4
#define CC   64
#define HC   256      // H*C
#define GG   256
#define NOUT 768

#define KP   304          // padded K (19 chunks of 16)
#define MP   50048        // padded M (391 * 128)
#define KCH  16
#define NCH  (KP / KCH)   // 19 chunks
#define NTILE (MP / 128 * 2)   // 782 tiles
#define GEMM_CTAS 296

// ---------------- scratch (device globals; no allocs allowed) ----------------
__device__ __nv_bfloat16 g_hb[(size_t)NN * HC];   // node features (bf16, 25.6 MB)
__device__ float g_asrc[NN * HH];
__device__ float g_adst[NN * HH];
__device__ int   g_deg[NN];
__device__ int   g_offs[NN + 1];
__device__ int   g_cursor[NN];
__device__ int   g_csr_src[EE];
__device__ float g_pool[GG * HC];
__device__ float g_cnt[GG];
__device__ int   g_bsum[64];
__device__ int   g_bpref[64];
__device__ __align__(16) __nv_bfloat16 g_xhi[(size_t)MP * KP];   // 30.4 MB
__device__ __align__(16) __nv_bfloat16 g_whi[HC * KP];           // [n][k]
__device__ __align__(16) __nv_bfloat16 g_wlo[HC * KP];

__device__ __forceinline__ float lrelu(float x, float s) { return x > 0.f ? x : s * x; }

__device__ __forceinline__ uint32_t smem_u32(const void* p) {
    uint32_t a;
    asm("{ .reg .u64 t; cvta.to.shared.u64 t, %1; cvt.u32.u64 %0, t; }" : "=r"(a) : "l"(p));
    return a;
}
__device__ __forceinline__ void cp_async16(uint32_t dst, const void* src) {
    asm volatile("cp.async.cg.shared.global [%0], [%1], 16;" :: "r"(dst), "l"(src));
}
__device__ __forceinline__ void cp_commit() { asm volatile("cp.async.commit_group;"); }
template <int N> __device__ __forceinline__ void cp_wait() {
    asm volatile("cp.async.wait_group %0;" :: "n"(N));
}
__device__ __forceinline__ void ldm_x4(uint32_t& r0, uint32_t& r1, uint32_t& r2, uint32_t& r3,
                                       uint32_t addr) {
    asm volatile("ldmatrix.sync.aligned.m8n8.x4.shared.b16 {%0,%1,%2,%3}, [%4];"
                 : "=r"(r0), "=r"(r1), "=r"(r2), "=r"(r3) : "r"(addr));
}
__device__ __forceinline__ void mma_bf16(float* d, const uint32_t* a, const uint32_t* b) {
    asm volatile("mma.sync.aligned.m16n8k16.row.col.f32.bf16.bf16.f32 "
                 "{%0,%1,%2,%3}, {%4,%5,%6,%7}, {%8,%9}, {%0,%1,%2,%3};"
                 : "+f"(d[0]), "+f"(d[1]), "+f"(d[2]), "+f"(d[3])
                 : "r"(a[0]), "r"(a[1]), "r"(a[2]), "r"(a[3]), "r"(b[0]), "r"(b[1]));
}

// ---------------- 0: zero scratch ----------------
__global__ void zero_kernel(int n_nodes) {
    int i = blockIdx.x * blockDim.x + threadIdx.x;
    if (i < n_nodes) g_deg[i] = 0;
    if (i < GG * HC) g_pool[i] = 0.f;
    if (i < GG)      g_cnt[i] = 0.f;
}

// ---------------- 1a: split W into bf16 hi/lo, transposed [n][k] -------------
__global__ void prep_w_kernel(const float* __restrict__ W) {
    int i = blockIdx.x * blockDim.x + threadIdx.x;   // n*KP + k
    if (i >= HC * KP) return;
    int n = i / KP, k = i % KP;
    float v = (k < NIN) ? W[(size_t)k * HC + n] : 0.f;
    __nv_bfloat16 hi = __float2bfloat16(v);
    __nv_bfloat16 lo = __float2bfloat16(v - __bfloat162float(hi));
    g_whi[i] = hi;
    g_wlo[i] = lo;
}

// ---------------- 1b: X -> bf16 (hi only), padded [MP][KP], vectorized -------
__global__ void prep_x_kernel(const float* __restrict__ X) {
    size_t q = (size_t)blockIdx.x * blockDim.x + threadIdx.x;   // 4-elem group
    if (q >= (size_t)MP * KP / 4) return;
    int m = (int)(q / (KP / 4));
    int k4 = (int)(q % (KP / 4)) * 4;
    float4 v;
    if (m < NN && k4 < NIN) {
        v = *(const float4*)(X + (size_t)m * NIN + k4);
    } else {
        v = make_float4(0.f, 0.f, 0.f, 0.f);
    }
    __nv_bfloat162 lo2 = __float22bfloat162_rn(make_float2(v.x, v.y));
    __nv_bfloat162 hi2 = __float22bfloat162_rn(make_float2(v.z, v.w));
    uint2 pack;
    pack.x = *(uint32_t*)&lo2;
    pack.y = *(uint32_t*)&hi2;
    *(uint2*)(g_xhi + (size_t)m * KP + k4) = pack;
}

// ---------------- 1c: persistent HMMA GEMM h = Xhi @ (Whi + Wlo) + att logits
#define ROWB    48
#define TILE_B  (128 * ROWB)     // 6144
#define STAGE_B (3 * TILE_B)     // 18432
#define STAGES  4
#define SM_GEMM_TOTAL (2048 + STAGES * STAGE_B)   // 75776

__global__ void __launch_bounds__(256, 2) gemm_tc_kernel(const float* __restrict__ att_src,
                                                         const float* __restrict__ att_dst) {
    extern __shared__ char smem[];
    uint32_t sb = smem_u32(smem);
    int tid = threadIdx.x;
    int lane = tid & 31;
    int wid = tid >> 5;
    int warp_m = wid & 3, warp_n = wid >> 2;

    float* s_att = (float*)smem;
    for (int i = tid; i < HC; i += 256) {
        s_att[i] = att_src[i];
        s_att[HC + i] = att_dst[i];
    }
    __syncthreads();

    const char* xhi_b = (const char*)g_xhi;
    const char* whi_b = (const char*)g_whi;
    const char* wlo_b = (const char*)g_wlo;

    int l_row = tid >> 1, l_half = tid & 1;

    for (int tile = blockIdx.x; tile < NTILE; tile += GEMM_CTAS) {
        int m0 = (tile >> 1) * 128;
        int n0 = (tile & 1) * 128;

        float acc[2][8][4];
#pragma unroll
        for (int mi = 0; mi < 2; mi++)
#pragma unroll
            for (int nj = 0; nj < 8; nj++)
#pragma unroll
                for (int q = 0; q < 4; q++) acc[mi][nj][q] = 0.f;

        auto prefetch = [&](int iter) {
            if (iter >= NCH) return;
            int stage = iter & (STAGES - 1);
            uint32_t base = sb + 2048 + stage * STAGE_B;
            size_t kb = (size_t)iter * 32;
            uint32_t doff = l_row * ROWB + l_half * 16;
            size_t aoff = (size_t)(m0 + l_row) * (KP * 2) + kb + l_half * 16;
            size_t boff = (size_t)(n0 + l_row) * (KP * 2) + kb + l_half * 16;
            cp_async16(base + doff,              xhi_b + aoff);
            cp_async16(base + TILE_B + doff,     whi_b + boff);
            cp_async16(base + 2 * TILE_B + doff, wlo_b + boff);
        };

        prefetch(0); cp_commit();
        prefetch(1); cp_commit();
        prefetch(2); cp_commit();

        for (int iter = 0; iter < NCH; iter++) {
            cp_wait<2>();
            __syncthreads();
            prefetch(iter + 3);
            cp_commit();

            uint32_t base = sb + 2048 + (iter & (STAGES - 1)) * STAGE_B;

            uint32_t ahi[2][4], bfr[8][2];
#pragma unroll
            for (int mi = 0; mi < 2; mi++) {
                int row = warp_m * 32 + mi * 16 + (lane & 15);
                uint32_t addr = base + row * ROWB + (lane >> 4) * 16;
                ldm_x4(ahi[mi][0], ahi[mi][1], ahi[mi][2], ahi[mi][3], addr);
            }
            {
                int grp = lane >> 3;
#pragma unroll
                for (int njp = 0; njp < 4; njp++) {
                    int nrow = warp_n * 64 + njp * 16 + (grp >> 1) * 8 + (lane & 7);
                    uint32_t addr = base + TILE_B + nrow * ROWB + (grp & 1) * 16;
                    ldm_x4(bfr[njp * 2][0], bfr[njp * 2][1],
                           bfr[njp * 2 + 1][0], bfr[njp * 2 + 1][1], addr);
                }
#pragma unroll
                for (int mi = 0; mi < 2; mi++)
#pragma unroll
                    for (int nj = 0; nj < 8; nj++)
                        mma_bf16(acc[mi][nj], ahi[mi], bfr[nj]);
#pragma unroll
                for (int njp = 0; njp < 4; njp++) {
                    int nrow = warp_n * 64 + njp * 16 + (grp >> 1) * 8 + (lane & 7);
                    uint32_t addr = base + 2 * TILE_B + nrow * ROWB + (grp & 1) * 16;
                    ldm_x4(bfr[njp * 2][0], bfr[njp * 2][1],
                           bfr[njp * 2 + 1][0], bfr[njp * 2 + 1][1], addr);
                }
#pragma unroll
                for (int mi = 0; mi < 2; mi++)
#pragma unroll
                    for (int nj = 0; nj < 8; nj++)
                        mma_bf16(acc[mi][nj], ahi[mi], bfr[nj]);
            }
        }

        // Epilogue: write g_hb (bf16) + fused attention-logit dots (fp32)
        int qlane = lane & 3;
        int colbase = n0 + warp_n * 64;
        int head = colbase >> 6;

#pragma unroll
        for (int mi = 0; mi < 2; mi++) {
            int rowA = m0 + warp_m * 32 + mi * 16 + (lane >> 2);
            int rowB = rowA + 8;
            float s1a = 0.f, s2a = 0.f, s1b = 0.f, s2b = 0.f;
#pragma unroll
            for (int nj = 0; nj < 8; nj++) {
                int c = colbase + nj * 8 + qlane * 2;
                float as0 = s_att[c], as1 = s_att[c + 1];
                float ad0 = s_att[HC + c], ad1 = s_att[HC + c + 1];
                float v0 = acc[mi][nj][0], v1 = acc[mi][nj][1];
                float v2 = acc[mi][nj][2], v3 = acc[mi][nj][3];
                s1a += v0 * as0 + v1 * as1;
                s2a += v0 * ad0 + v1 * ad1;
                s1b += v2 * as0 + v3 * as1;
                s2b += v2 * ad0 + v3 * ad1;
                if (rowA < NN)
                    *(__nv_bfloat162*)(g_hb + (size_t)rowA * HC + c) =
                        __float22bfloat162_rn(make_float2(v0, v1));
                if (rowB < NN)
                    *(__nv_bfloat162*)(g_hb + (size_t)rowB * HC + c) =
                        __float22bfloat162_rn(make_float2(v2, v3));
            }
            s1a += __shfl_xor_sync(0xFFFFFFFF, s1a, 1); s1a += __shfl_xor_sync(0xFFFFFFFF, s1a, 2);
            s2a += __shfl_xor_sync(0xFFFFFFFF, s2a, 1); s2a += __shfl_xor_sync(0xFFFFFFFF, s2a, 2);
            s1b += __shfl_xor_sync(0xFFFFFFFF, s1b, 1); s1b += __shfl_xor_sync(0xFFFFFFFF, s1b, 2);
            s2b += __shfl_xor_sync(0xFFFFFFFF, s2b, 1); s2b += __shfl_xor_sync(0xFFFFFFFF, s2b, 2);
            if (qlane == 0) {
                if (rowA < NN) { g_asrc[rowA * HH + head] = s1a; g_adst[rowA * HH + head] = s2a; }
                if (rowB < NN) { g_asrc[rowB * HH + head] = s1b; g_adst[rowB * HH + head] = s2b; }
            }
        }
        __syncthreads();
    }
}

// ---------------- 3: histograms ----------------
__global__ void deg_kernel(const int* __restrict__ dst, int E) {
    int i = blockIdx.x * blockDim.x + threadIdx.x;
    if (i < E) atomicAdd(&g_deg[dst[i]], 1);
}

__global__ void cnt_kernel(const int* __restrict__ batch, int n_nodes) {
    int i = blockIdx.x * blockDim.x + threadIdx.x;
    if (i < n_nodes) atomicAdd(&g_cnt[batch[i]], 1.f);
}

// ---------------- 4: exclusive scan of degrees ----------------
__global__ void scan1_kernel(int n_nodes) {
    __shared__ int s[1024];
    int t = threadIdx.x;
    int gid = blockIdx.x * 1024 + t;
    int v = (gid < n_nodes) ? g_deg[gid] : 0;
    s[t] = v;
    __syncthreads();
    for (int d = 1; d < 1024; d <<= 1) {
        int x = (t >= d) ? s[t - d] : 0;
        __syncthreads();
        s[t] += x;
        __syncthreads();
    }
    if (gid < n_nodes) g_offs[gid] = s[t] - v;
    if (t == 1023) g_bsum[blockIdx.x] = s[1023];
}

__global__ void scan2_kernel(int nb) {
    int acc = 0;
    for (int i = 0; i < nb; i++) { int v = g_bsum[i]; g_bpref[i] = acc; acc += v; }
}

__global__ void scan3_kernel(int n_nodes, int E) {
    int gid = blockIdx.x * 1024 + threadIdx.x;
    if (gid < n_nodes) {
        int v = g_offs[gid] + g_bpref[blockIdx.x];
        g_offs[gid] = v;
        g_cursor[gid] = v;
    }
    if (gid == 0) g_offs[n_nodes] = E;
}

// ---------------- 5: scatter src ids into CSR ----------------
__global__ void scatter_kernel(const int* __restrict__ src,
                               const int* __restrict__ dst, int E) {
    int i = blockIdx.x * blockDim.x + threadIdx.x;
    if (i < E) {
        int d = dst[i];
        int pos = atomicAdd(&g_cursor[d], 1);
        g_csr_src[pos] = src[i];
    }
}

// ---------------- 6: single-pass softmax + aggregate + act + pool (warp/node)
// Software-pipelined edge loop: batch 4, depth 2 — next batch's indices,
// logits and rows are fetched before the current batch is processed.
__device__ __forceinline__ void bf8_to_f(uint4 r, float* f) {
    __nv_bfloat162* p = (__nv_bfloat162*)&r;
#pragma unroll
    for (int j = 0; j < 4; j++) {
        float2 t = __bfloat1622float2(p[j]);
        f[2 * j] = t.x;
        f[2 * j + 1] = t.y;
    }
}

__global__ void __launch_bounds__(256) aggregate_kernel(const int* __restrict__ batch,
                                                        const float* __restrict__ bias,
                                                        int n_nodes) {
    __shared__ float sv[8][HC];
    __shared__ int sg[8];
    int wip = threadIdx.x >> 5;
    int lane = threadIdx.x & 31;
    int d = blockIdx.x * 8 + wip;
    int hd = lane >> 3;
    bool valid = d < n_nodes;

    if (valid) {
        float ad_d = g_adst[d * HH + hd];
        float as_d = g_asrc[d * HH + hd];
        float w_self = __expf(lrelu(as_d + ad_d, 0.2f));
        int beg = g_offs[d], end = g_offs[d + 1];

        float hv[8], acc[8];
        bf8_to_f(*(const uint4*)(g_hb + (size_t)d * HC + lane * 8), hv);
        float den = w_self;
#pragma unroll
        for (int j = 0; j < 8; j++) acc[j] = hv[j] * w_self;

        // double-buffered 4-batch pipeline
        int   sA[2][4];
        float eA[2][4];
        uint4 rA[2][4];

        auto fetch = [&](int b, int k) {
#pragma unroll
            for (int u = 0; u < 4; u++) sA[b][u] = g_csr_src[k + u];
#pragma unroll
            for (int u = 0; u < 4; u++) eA[b][u] = g_asrc[sA[b][u] * HH + hd];
#pragma unroll
            for (int u = 0; u < 4; u++)
                rA[b][u] = *(const uint4*)(g_hb + (size_t)sA[b][u] * HC + lane * 8);
        };

        int kp = beg;   // next batch to process
        int kf = beg;   // next batch to fetch
        int cur = 0;
        if (kf + 4 <= end) { fetch(0, kf); kf += 4; }
        while (kp + 4 <= end) {
            int nxt = cur ^ 1;
            if (kf + 4 <= end) { fetch(nxt, kf); kf += 4; }
            // process cur
            float wA[4];
#pragma unroll
            for (int u = 0; u < 4; u++) wA[u] = __expf(lrelu(eA[cur][u] + ad_d, 0.2f));
#pragma unroll
            for (int u = 0; u < 4; u++) den += wA[u];
#pragma unroll
            for (int u = 0; u < 4; u++) {
                bf8_to_f(rA[cur][u], hv);
#pragma unroll
                for (int j = 0; j < 8; j++) acc[j] += wA[u] * hv[j];
            }
            kp += 4;
            cur = nxt;
        }
        for (; kp < end; kp++) {
            int s = g_csr_src[kp];
            float e = lrelu(g_asrc[s * HH + hd] + ad_d, 0.2f);
            float w = __expf(e);
            den += w;
            bf8_to_f(*(const uint4*)(g_hb + (size_t)s * HC + lane * 8), hv);
#pragma unroll
            for (int j = 0; j < 8; j++) acc[j] += w * hv[j];
        }

        float inv = 1.f / den;
        const float* b = bias + lane * 8;
#pragma unroll
        for (int j = 0; j < 8; j++)
            sv[wip][lane * 8 + j] = lrelu(acc[j] * inv + b[j], 0.01f);
        if (lane == 0) sg[wip] = batch[d];
    } else if (lane == 0) {
        sg[wip] = -1;
    }
    __syncthreads();

    // cross-warp pool reduction: batch is sorted, so a block usually spans 1 graph
    int c = threadIdx.x;
    int g0 = sg[0];
    float s0 = 0.f;
#pragma unroll
    for (int w = 0; w < 8; w++) {
        int gw = sg[w];
        if (gw < 0) continue;
        float val = sv[w][c];
        if (gw == g0) s0 += val;
        else atomicAdd(&g_pool[gw * HC + c], val);
    }
    if (g0 >= 0) atomicAdd(&g_pool[g0 * HC + c], s0);
}

// ---------------- 7: pooled @ fc1_w + fc1_b (8 graphs per block) -------------
__global__ void __launch_bounds__(256) final_gemm_kernel(const float* __restrict__ fc1_w,
                                                         const float* __restrict__ fc1_b,
                                                         float* __restrict__ out) {
    __shared__ float prow[8][HC];
    int g0 = blockIdx.y * 8;
    int tid = threadIdx.x;
    for (int i = tid; i < 8 * HC; i += 256) {
        int g = i >> 8, k = i & 255;
        float ic = 1.f / fmaxf(g_cnt[g0 + g], 1.f);
        prow[g][k] = g_pool[(g0 + g) * HC + k] * ic;
    }
    __syncthreads();
    int o = blockIdx.x * 256 + tid;
    float bv = fc1_b[o];
    float s[8];
#pragma unroll
    for (int g = 0; g < 8; g++) s[g] = bv;
#pragma unroll 4
    for (int k = 0; k < HC; k++) {
        float w = fc1_w[k * NOUT + o];
#pragma unroll
        for (int g = 0; g < 8; g++) s[g] += prow[g][k] * w;
    }
#pragma unroll
    for (int g = 0; g < 8; g++) out[(g0 + g) * NOUT + o] = s[g];
}

// ---------------- launch ----------------
extern "C" void kernel_launch(void* const* d_in, const int* in_sizes, int n_in,
                              void* d_out, int out_size) {
    const float* x       = (const float*)d_in[0];
    const int*   ei      = (const int*)d_in[1];
    const int*   batch   = (const int*)d_in[2];
    const float* lin_w   = (const float*)d_in[3];
    const float* att_src = (const float*)d_in[4];
    const float* att_dst = (const float*)d_in[5];
    const float* bias    = (const float*)d_in[6];
    const float* fc1_w   = (const float*)d_in[7];
    const float* fc1_b   = (const float*)d_in[8];
    float* out = (float*)d_out;

    int n_nodes = in_sizes[2];        // 50000
    int E = in_sizes[1] / 2;          // 800000
    const int* src = ei;
    const int* dst = ei + E;

    static cudaStream_t sB = nullptr;
    static cudaEvent_t evFork = nullptr, evJoin = nullptr, evW = nullptr;
    if (sB == nullptr) {
        cudaStreamCreateWithFlags(&sB, cudaStreamNonBlocking);
        cudaEventCreateWithFlags(&evFork, cudaEventDisableTiming);
        cudaEventCreateWithFlags(&evJoin, cudaEventDisableTiming);
        cudaEventCreateWithFlags(&evW, cudaEventDisableTiming);
        cudaFuncSetAttribute(gemm_tc_kernel, cudaFuncAttributeMaxDynamicSharedMemorySize,
                             SM_GEMM_TOTAL);
    }

    // Fork: side stream handles W-split + CSR build while main does X prep.
    cudaEventRecord(evFork, 0);
    cudaStreamWaitEvent(sB, evFork, 0);

    // --- side stream: W split first (gemm dependency), then CSR chain ---
    prep_w_kernel<<<(HC * KP + 255) / 256, 256, 0, sB>>>(lin_w);
    cudaEventRecord(evW, sB);
    int zero_n = (n_nodes > GG * HC) ? n_nodes : GG * HC;
    zero_kernel<<<(zero_n + 255) / 256, 256, 0, sB>>>(n_nodes);
    deg_kernel<<<(E + 255) / 256, 256, 0, sB>>>(dst, E);
    cnt_kernel<<<(n_nodes + 255) / 256, 256, 0, sB>>>(batch, n_nodes);
    int nb = (n_nodes + 1023) / 1024;
    scan1_kernel<<<nb, 1024, 0, sB>>>(n_nodes);
    scan2_kernel<<<1, 1, 0, sB>>>(nb);
    scan3_kernel<<<nb, 1024, 0, sB>>>(n_nodes, E);
    scatter_kernel<<<(E + 255) / 256, 256, 0, sB>>>(src, dst, E);
    cudaEventRecord(evJoin, sB);

    // --- main stream: X prep, wait for W, persistent GEMM ---
    {
        size_t tot = (size_t)MP * KP / 4;
        prep_x_kernel<<<(int)((tot + 255) / 256), 256>>>(x);
    }
    cudaStreamWaitEvent(0, evW, 0);
    gemm_tc_kernel<<<GEMM_CTAS, 256, SM_GEMM_TOTAL>>>(att_src, att_dst);

    // Join, then aggregate + final
    cudaStreamWaitEvent(0, evJoin, 0);
    aggregate_kernel<<<(n_nodes + 7) / 8, 256>>>(batch, bias, n_nodes);

    dim3 fg(NOUT / 256, GG / 8);
    final_gemm_kernel<<<fg, 256>>>(fc1_w, fc1_b, out);
}

// round 15
// speedup vs baseline: 1.2302x; 1.2302x over previous
#include <cuda_runtime.h>
#include <cuda_bf16.h>
#include <math.h>
#include <stdint.h>

// Problem constants (fixed by the reference)
#define NN   50000
#define EE   800000
#define NIN  300
#define HH   4
#define CC   64
#define HC   256      // H*C
#define GG   256
#define NOUT 768

#define KP   304          // padded K (19 chunks of 16)
#define MP   50048        // padded M (391 * 128)
#define KCH  16
#define NCH  (KP / KCH)   // 19 chunks

// ---------------- scratch (device globals; no allocs allowed) ----------------
__device__ __nv_bfloat16 g_hb[(size_t)NN * HC];   // node features (bf16, 25.6 MB)
__device__ float g_asrc[NN * HH];
__device__ float g_adst[NN * HH];
__device__ int   g_deg[NN];
__device__ int   g_offs[NN + 1];
__device__ int   g_cursor[NN];
__device__ int   g_csr_src[EE];
__device__ float g_pool[GG * HC];
__device__ float g_cnt[GG];
__device__ int   g_bsum[64];
__device__ int   g_bpref[64];
__device__ __align__(16) __nv_bfloat16 g_xhi[(size_t)MP * KP];   // 30.4 MB
__device__ __align__(16) __nv_bfloat16 g_whi[HC * KP];           // [n][k]
__device__ __align__(16) __nv_bfloat16 g_wlo[HC * KP];

__device__ __forceinline__ float lrelu(float x, float s) { return x > 0.f ? x : s * x; }

__device__ __forceinline__ uint32_t smem_u32(const void* p) {
    uint32_t a;
    asm("{ .reg .u64 t; cvta.to.shared.u64 t, %1; cvt.u32.u64 %0, t; }" : "=r"(a) : "l"(p));
    return a;
}
__device__ __forceinline__ void cp_async16(uint32_t dst, const void* src) {
    asm volatile("cp.async.cg.shared.global [%0], [%1], 16;" :: "r"(dst), "l"(src));
}
__device__ __forceinline__ void cp_commit() { asm volatile("cp.async.commit_group;"); }
template <int N> __device__ __forceinline__ void cp_wait() {
    asm volatile("cp.async.wait_group %0;" :: "n"(N));
}
__device__ __forceinline__ void ldm_x4(uint32_t& r0, uint32_t& r1, uint32_t& r2, uint32_t& r3,
                                       uint32_t addr) {
    asm volatile("ldmatrix.sync.aligned.m8n8.x4.shared.b16 {%0,%1,%2,%3}, [%4];"
                 : "=r"(r0), "=r"(r1), "=r"(r2), "=r"(r3) : "r"(addr));
}
__device__ __forceinline__ void mma_bf16(float* d, const uint32_t* a, const uint32_t* b) {
    asm volatile("mma.sync.aligned.m16n8k16.row.col.f32.bf16.bf16.f32 "
                 "{%0,%1,%2,%3}, {%4,%5,%6,%7}, {%8,%9}, {%0,%1,%2,%3};"
                 : "+f"(d[0]), "+f"(d[1]), "+f"(d[2]), "+f"(d[3])
                 : "r"(a[0]), "r"(a[1]), "r"(a[2]), "r"(a[3]), "r"(b[0]), "r"(b[1]));
}
// L2-only (bypass L1) 16B load for streaming gathers
__device__ __forceinline__ uint4 ldcg16(const void* p) {
    uint4 r;
    asm volatile("ld.global.cg.v4.u32 {%0,%1,%2,%3}, [%4];"
                 : "=r"(r.x), "=r"(r.y), "=r"(r.z), "=r"(r.w) : "l"(p));
    return r;
}

// ---------------- 0: zero scratch ----------------
__global__ void zero_kernel(int n_nodes) {
    int i = blockIdx.x * blockDim.x + threadIdx.x;
    if (i < n_nodes) g_deg[i] = 0;
    if (i < GG * HC) g_pool[i] = 0.f;
    if (i < GG)      g_cnt[i] = 0.f;
}

// ---------------- 1a: split W into bf16 hi/lo, transposed [n][k] -------------
__global__ void prep_w_kernel(const float* __restrict__ W) {
    int i = blockIdx.x * blockDim.x + threadIdx.x;   // n*KP + k
    if (i >= HC * KP) return;
    int n = i / KP, k = i % KP;
    float v = (k < NIN) ? W[(size_t)k * HC + n] : 0.f;
    __nv_bfloat16 hi = __float2bfloat16(v);
    __nv_bfloat16 lo = __float2bfloat16(v - __bfloat162float(hi));
    g_whi[i] = hi;
    g_wlo[i] = lo;
}

// ---------------- 1b: X -> bf16 (hi only), padded [MP][KP], vectorized -------
__global__ void prep_x_kernel(const float* __restrict__ X) {
    size_t q = (size_t)blockIdx.x * blockDim.x + threadIdx.x;   // 4-elem group
    if (q >= (size_t)MP * KP / 4) return;
    int m = (int)(q / (KP / 4));
    int k4 = (int)(q % (KP / 4)) * 4;
    float4 v;
    if (m < NN && k4 < NIN) {
        v = *(const float4*)(X + (size_t)m * NIN + k4);   // NIN%4==0: in-row, aligned
    } else {
        v = make_float4(0.f, 0.f, 0.f, 0.f);
    }
    __nv_bfloat162 lo2 = __float22bfloat162_rn(make_float2(v.x, v.y));
    __nv_bfloat162 hi2 = __float22bfloat162_rn(make_float2(v.z, v.w));
    uint2 pack;
    pack.x = *(uint32_t*)&lo2;
    pack.y = *(uint32_t*)&hi2;
    *(uint2*)(g_xhi + (size_t)m * KP + k4) = pack;
}

// ---------------- 1c: HMMA GEMM h = Xhi @ (Whi + Wlo) + fused att logits -----
// CTA tile 128(M) x 128(N); 8 warps in 4x2; warp tile 32 x 64.
// Per K-chunk (16 elems) the stage holds {AHI, BHI, BLO}.
#define ROWB    48
#define TILE_B  (128 * ROWB)     // 6144
#define STAGE_B (3 * TILE_B)     // 18432
#define STAGES  4
#define SM_GEMM_TOTAL (2048 + STAGES * STAGE_B)   // 75776

__global__ void __launch_bounds__(256, 2) gemm_tc_kernel(const float* __restrict__ att_src,
                                                         const float* __restrict__ att_dst) {
    extern __shared__ char smem[];
    uint32_t sb = smem_u32(smem);
    int tid = threadIdx.x;
    int lane = tid & 31;
    int wid = tid >> 5;
    int warp_m = wid & 3, warp_n = wid >> 2;
    int m0 = blockIdx.x * 128;
    int n0 = blockIdx.y * 128;

    float* s_att = (float*)smem;
    for (int i = tid; i < HC; i += 256) {
        s_att[i] = att_src[i];
        s_att[HC + i] = att_dst[i];
    }

    const char* xhi_b = (const char*)g_xhi;
    const char* whi_b = (const char*)g_whi;
    const char* wlo_b = (const char*)g_wlo;

    float acc[2][8][4];
#pragma unroll
    for (int mi = 0; mi < 2; mi++)
#pragma unroll
        for (int nj = 0; nj < 8; nj++)
#pragma unroll
            for (int q = 0; q < 4; q++) acc[mi][nj][q] = 0.f;

    int l_row = tid >> 1, l_half = tid & 1;

    auto prefetch = [&](int iter) {
        if (iter >= NCH) return;
        int stage = iter & (STAGES - 1);
        uint32_t base = sb + 2048 + stage * STAGE_B;
        size_t kb = (size_t)iter * 32;            // 16 bf16 = 32 B
        uint32_t doff = l_row * ROWB + l_half * 16;
        size_t aoff = (size_t)(m0 + l_row) * (KP * 2) + kb + l_half * 16;
        size_t boff = (size_t)(n0 + l_row) * (KP * 2) + kb + l_half * 16;
        cp_async16(base + doff,              xhi_b + aoff);
        cp_async16(base + TILE_B + doff,     whi_b + boff);
        cp_async16(base + 2 * TILE_B + doff, wlo_b + boff);
    };

    prefetch(0); cp_commit();
    prefetch(1); cp_commit();
    prefetch(2); cp_commit();

    for (int iter = 0; iter < NCH; iter++) {
        cp_wait<2>();
        __syncthreads();
        prefetch(iter + 3);
        cp_commit();

        uint32_t base = sb + 2048 + (iter & (STAGES - 1)) * STAGE_B;

        uint32_t ahi[2][4], bfr[8][2];
#pragma unroll
        for (int mi = 0; mi < 2; mi++) {
            int row = warp_m * 32 + mi * 16 + (lane & 15);
            uint32_t addr = base + row * ROWB + (lane >> 4) * 16;
            ldm_x4(ahi[mi][0], ahi[mi][1], ahi[mi][2], ahi[mi][3], addr);
        }
        {
            int grp = lane >> 3;
            // BHI
#pragma unroll
            for (int njp = 0; njp < 4; njp++) {
                int nrow = warp_n * 64 + njp * 16 + (grp >> 1) * 8 + (lane & 7);
                uint32_t addr = base + TILE_B + nrow * ROWB + (grp & 1) * 16;
                ldm_x4(bfr[njp * 2][0], bfr[njp * 2][1],
                       bfr[njp * 2 + 1][0], bfr[njp * 2 + 1][1], addr);
            }
#pragma unroll
            for (int mi = 0; mi < 2; mi++)
#pragma unroll
                for (int nj = 0; nj < 8; nj++)
                    mma_bf16(acc[mi][nj], ahi[mi], bfr[nj]);
            // BLO (reuse bfr registers)
#pragma unroll
            for (int njp = 0; njp < 4; njp++) {
                int nrow = warp_n * 64 + njp * 16 + (grp >> 1) * 8 + (lane & 7);
                uint32_t addr = base + 2 * TILE_B + nrow * ROWB + (grp & 1) * 16;
                ldm_x4(bfr[njp * 2][0], bfr[njp * 2][1],
                       bfr[njp * 2 + 1][0], bfr[njp * 2 + 1][1], addr);
            }
#pragma unroll
            for (int mi = 0; mi < 2; mi++)
#pragma unroll
                for (int nj = 0; nj < 8; nj++)
                    mma_bf16(acc[mi][nj], ahi[mi], bfr[nj]);
        }
    }

    // Epilogue: write g_hb (bf16) + fused attention-logit dots (fp32)
    int qlane = lane & 3;
    int colbase = n0 + warp_n * 64;
    int head = colbase >> 6;

#pragma unroll
    for (int mi = 0; mi < 2; mi++) {
        int rowA = m0 + warp_m * 32 + mi * 16 + (lane >> 2);
        int rowB = rowA + 8;
        float s1a = 0.f, s2a = 0.f, s1b = 0.f, s2b = 0.f;
#pragma unroll
        for (int nj = 0; nj < 8; nj++) {
            int c = colbase + nj * 8 + qlane * 2;
            float as0 = s_att[c], as1 = s_att[c + 1];
            float ad0 = s_att[HC + c], ad1 = s_att[HC + c + 1];
            float v0 = acc[mi][nj][0], v1 = acc[mi][nj][1];
            float v2 = acc[mi][nj][2], v3 = acc[mi][nj][3];
            s1a += v0 * as0 + v1 * as1;
            s2a += v0 * ad0 + v1 * ad1;
            s1b += v2 * as0 + v3 * as1;
            s2b += v2 * ad0 + v3 * ad1;
            if (rowA < NN)
                *(__nv_bfloat162*)(g_hb + (size_t)rowA * HC + c) =
                    __float22bfloat162_rn(make_float2(v0, v1));
            if (rowB < NN)
                *(__nv_bfloat162*)(g_hb + (size_t)rowB * HC + c) =
                    __float22bfloat162_rn(make_float2(v2, v3));
        }
        s1a += __shfl_xor_sync(0xFFFFFFFF, s1a, 1); s1a += __shfl_xor_sync(0xFFFFFFFF, s1a, 2);
        s2a += __shfl_xor_sync(0xFFFFFFFF, s2a, 1); s2a += __shfl_xor_sync(0xFFFFFFFF, s2a, 2);
        s1b += __shfl_xor_sync(0xFFFFFFFF, s1b, 1); s1b += __shfl_xor_sync(0xFFFFFFFF, s1b, 2);
        s2b += __shfl_xor_sync(0xFFFFFFFF, s2b, 1); s2b += __shfl_xor_sync(0xFFFFFFFF, s2b, 2);
        if (qlane == 0) {
            if (rowA < NN) { g_asrc[rowA * HH + head] = s1a; g_adst[rowA * HH + head] = s2a; }
            if (rowB < NN) { g_asrc[rowB * HH + head] = s1b; g_adst[rowB * HH + head] = s2b; }
        }
    }
}

// ---------------- 3: histograms ----------------
__global__ void deg_kernel(const int* __restrict__ dst, int E) {
    int i = blockIdx.x * blockDim.x + threadIdx.x;
    if (i < E) atomicAdd(&g_deg[dst[i]], 1);
}

__global__ void cnt_kernel(const int* __restrict__ batch, int n_nodes) {
    int i = blockIdx.x * blockDim.x + threadIdx.x;
    if (i < n_nodes) atomicAdd(&g_cnt[batch[i]], 1.f);
}

// ---------------- 4: exclusive scan of degrees ----------------
__global__ void scan1_kernel(int n_nodes) {
    __shared__ int s[1024];
    int t = threadIdx.x;
    int gid = blockIdx.x * 1024 + t;
    int v = (gid < n_nodes) ? g_deg[gid] : 0;
    s[t] = v;
    __syncthreads();
    for (int d = 1; d < 1024; d <<= 1) {
        int x = (t >= d) ? s[t - d] : 0;
        __syncthreads();
        s[t] += x;
        __syncthreads();
    }
    if (gid < n_nodes) g_offs[gid] = s[t] - v;
    if (t == 1023) g_bsum[blockIdx.x] = s[1023];
}

__global__ void scan2_kernel(int nb) {
    int acc = 0;
    for (int i = 0; i < nb; i++) { int v = g_bsum[i]; g_bpref[i] = acc; acc += v; }
}

__global__ void scan3_kernel(int n_nodes, int E) {
    int gid = blockIdx.x * 1024 + threadIdx.x;
    if (gid < n_nodes) {
        int v = g_offs[gid] + g_bpref[blockIdx.x];
        g_offs[gid] = v;
        g_cursor[gid] = v;
    }
    if (gid == 0) g_offs[n_nodes] = E;
}

// ---------------- 5: scatter src ids into CSR ----------------
__global__ void scatter_kernel(const int* __restrict__ src,
                               const int* __restrict__ dst, int E) {
    int i = blockIdx.x * blockDim.x + threadIdx.x;
    if (i < E) {
        int d = dst[i];
        int pos = atomicAdd(&g_cursor[d], 1);
        g_csr_src[pos] = src[i];
    }
}

// ---------------- 6: single-pass softmax + aggregate + act + pool (warp/node)
// (R10 structure — best measured config; row gathers via ld.global.cg)
__device__ __forceinline__ void bf8_to_f(uint4 r, float* f) {
    __nv_bfloat162* p = (__nv_bfloat162*)&r;
#pragma unroll
    for (int j = 0; j < 4; j++) {
        float2 t = __bfloat1622float2(p[j]);
        f[2 * j] = t.x;
        f[2 * j + 1] = t.y;
    }
}

__global__ void __launch_bounds__(256) aggregate_kernel(const int* __restrict__ batch,
                                                        const float* __restrict__ bias,
                                                        int n_nodes) {
    __shared__ float sv[8][HC];
    __shared__ int sg[8];
    int wip = threadIdx.x >> 5;
    int lane = threadIdx.x & 31;
    int d = blockIdx.x * 8 + wip;
    int hd = lane >> 3;
    bool valid = d < n_nodes;

    if (valid) {
        float ad_d = g_adst[d * HH + hd];
        float as_d = g_asrc[d * HH + hd];
        float w_self = __expf(lrelu(as_d + ad_d, 0.2f));
        int beg = g_offs[d], end = g_offs[d + 1];

        float hv[8], acc[8];
        bf8_to_f(ldcg16(g_hb + (size_t)d * HC + lane * 8), hv);
        float den = w_self;
#pragma unroll
        for (int j = 0; j < 8; j++) acc[j] = hv[j] * w_self;

        int k = beg;
        for (; k + 8 <= end; k += 8) {
            int sA[8];
            float eA[8], wA[8];
            uint4 rA[8];
#pragma unroll
            for (int u = 0; u < 8; u++) sA[u] = g_csr_src[k + u];
#pragma unroll
            for (int u = 0; u < 8; u++) eA[u] = g_asrc[sA[u] * HH + hd];
#pragma unroll
            for (int u = 0; u < 8; u++)
                rA[u] = ldcg16(g_hb + (size_t)sA[u] * HC + lane * 8);
#pragma unroll
            for (int u = 0; u < 8; u++) wA[u] = __expf(lrelu(eA[u] + ad_d, 0.2f));
#pragma unroll
            for (int u = 0; u < 8; u++) den += wA[u];
#pragma unroll
            for (int u = 0; u < 8; u++) {
                bf8_to_f(rA[u], hv);
#pragma unroll
                for (int j = 0; j < 8; j++) acc[j] += wA[u] * hv[j];
            }
        }
        for (; k + 4 <= end; k += 4) {
            int s0 = g_csr_src[k],     s1 = g_csr_src[k + 1];
            int s2 = g_csr_src[k + 2], s3 = g_csr_src[k + 3];
            float e0 = g_asrc[s0 * HH + hd], e1 = g_asrc[s1 * HH + hd];
            float e2 = g_asrc[s2 * HH + hd], e3 = g_asrc[s3 * HH + hd];
            uint4 r0 = ldcg16(g_hb + (size_t)s0 * HC + lane * 8);
            uint4 r1 = ldcg16(g_hb + (size_t)s1 * HC + lane * 8);
            uint4 r2 = ldcg16(g_hb + (size_t)s2 * HC + lane * 8);
            uint4 r3 = ldcg16(g_hb + (size_t)s3 * HC + lane * 8);
            float w0 = __expf(lrelu(e0 + ad_d, 0.2f));
            float w1 = __expf(lrelu(e1 + ad_d, 0.2f));
            float w2 = __expf(lrelu(e2 + ad_d, 0.2f));
            float w3 = __expf(lrelu(e3 + ad_d, 0.2f));
            den += (w0 + w1) + (w2 + w3);
            bf8_to_f(r0, hv);
#pragma unroll
            for (int j = 0; j < 8; j++) acc[j] += w0 * hv[j];
            bf8_to_f(r1, hv);
#pragma unroll
            for (int j = 0; j < 8; j++) acc[j] += w1 * hv[j];
            bf8_to_f(r2, hv);
#pragma unroll
            for (int j = 0; j < 8; j++) acc[j] += w2 * hv[j];
            bf8_to_f(r3, hv);
#pragma unroll
            for (int j = 0; j < 8; j++) acc[j] += w3 * hv[j];
        }
        for (; k < end; k++) {
            int s = g_csr_src[k];
            float e = lrelu(g_asrc[s * HH + hd] + ad_d, 0.2f);
            float w = __expf(e);
            den += w;
            bf8_to_f(ldcg16(g_hb + (size_t)s * HC + lane * 8), hv);
#pragma unroll
            for (int j = 0; j < 8; j++) acc[j] += w * hv[j];
        }
        float inv = 1.f / den;
        const float* b = bias + lane * 8;
#pragma unroll
        for (int j = 0; j < 8; j++)
            sv[wip][lane * 8 + j] = lrelu(acc[j] * inv + b[j], 0.01f);
        if (lane == 0) sg[wip] = batch[d];
    } else if (lane == 0) {
        sg[wip] = -1;
    }
    __syncthreads();

    // cross-warp pool reduction: batch is sorted, so a block usually spans 1 graph
    int c = threadIdx.x;
    int g0 = sg[0];
    float s0 = 0.f;
#pragma unroll
    for (int w = 0; w < 8; w++) {
        int gw = sg[w];
        if (gw < 0) continue;
        float val = sv[w][c];
        if (gw == g0) s0 += val;
        else atomicAdd(&g_pool[gw * HC + c], val);
    }
    if (g0 >= 0) atomicAdd(&g_pool[g0 * HC + c], s0);
}

// ---------------- 7: pooled @ fc1_w + fc1_b (8 graphs per block) -------------
__global__ void __launch_bounds__(256) final_gemm_kernel(const float* __restrict__ fc1_w,
                                                         const float* __restrict__ fc1_b,
                                                         float* __restrict__ out) {
    __shared__ float prow[8][HC];
    int g0 = blockIdx.y * 8;
    int tid = threadIdx.x;
    for (int i = tid; i < 8 * HC; i += 256) {
        int g = i >> 8, k = i & 255;
        float ic = 1.f / fmaxf(g_cnt[g0 + g], 1.f);
        prow[g][k] = g_pool[(g0 + g) * HC + k] * ic;
    }
    __syncthreads();
    int o = blockIdx.x * 256 + tid;
    float bv = fc1_b[o];
    float s[8];
#pragma unroll
    for (int g = 0; g < 8; g++) s[g] = bv;
#pragma unroll 4
    for (int k = 0; k < HC; k++) {
        float w = fc1_w[k * NOUT + o];
#pragma unroll
        for (int g = 0; g < 8; g++) s[g] += prow[g][k] * w;
    }
#pragma unroll
    for (int g = 0; g < 8; g++) out[(g0 + g) * NOUT + o] = s[g];
}

// ---------------- launch ----------------
extern "C" void kernel_launch(void* const* d_in, const int* in_sizes, int n_in,
                              void* d_out, int out_size) {
    const float* x       = (const float*)d_in[0];
    const int*   ei      = (const int*)d_in[1];
    const int*   batch   = (const int*)d_in[2];
    const float* lin_w   = (const float*)d_in[3];
    const float* att_src = (const float*)d_in[4];
    const float* att_dst = (const float*)d_in[5];
    const float* bias    = (const float*)d_in[6];
    const float* fc1_w   = (const float*)d_in[7];
    const float* fc1_b   = (const float*)d_in[8];
    float* out = (float*)d_out;

    int n_nodes = in_sizes[2];        // 50000
    int E = in_sizes[1] / 2;          // 800000
    const int* src = ei;
    const int* dst = ei + E;

    // One-time host-side setup (streams/events are host objects, no device mem)
    static cudaStream_t sB = nullptr;
    static cudaEvent_t evFork = nullptr, evJoin = nullptr;
    if (sB == nullptr) {
        cudaStreamCreateWithFlags(&sB, cudaStreamNonBlocking);
        cudaEventCreateWithFlags(&evFork, cudaEventDisableTiming);
        cudaEventCreateWithFlags(&evJoin, cudaEventDisableTiming);
        cudaFuncSetAttribute(gemm_tc_kernel, cudaFuncAttributeMaxDynamicSharedMemorySize,
                             SM_GEMM_TOTAL);
    }

    // Fork: CSR-build chain on sB runs concurrently with prep+GEMM on stream 0.
    cudaEventRecord(evFork, 0);
    cudaStreamWaitEvent(sB, evFork, 0);

    // --- side stream: zero + CSR build + counts ---
    int zero_n = (n_nodes > GG * HC) ? n_nodes : GG * HC;
    zero_kernel<<<(zero_n + 255) / 256, 256, 0, sB>>>(n_nodes);
    deg_kernel<<<(E + 255) / 256, 256, 0, sB>>>(dst, E);
    cnt_kernel<<<(n_nodes + 255) / 256, 256, 0, sB>>>(batch, n_nodes);
    int nb = (n_nodes + 1023) / 1024;
    scan1_kernel<<<nb, 1024, 0, sB>>>(n_nodes);
    scan2_kernel<<<1, 1, 0, sB>>>(nb);
    scan3_kernel<<<nb, 1024, 0, sB>>>(n_nodes, E);
    scatter_kernel<<<(E + 255) / 256, 256, 0, sB>>>(src, dst, E);
    cudaEventRecord(evJoin, sB);

    // --- main stream: bf16 prep + tensor-core GEMM ---
    prep_w_kernel<<<(HC * KP + 255) / 256, 256>>>(lin_w);
    {
        size_t tot = (size_t)MP * KP / 4;
        prep_x_kernel<<<(int)((tot + 255) / 256), 256>>>(x);
    }
    dim3 gg(MP / 128, 2);
    gemm_tc_kernel<<<gg, 256, SM_GEMM_TOTAL>>>(att_src, att_dst);

    // Join, then aggregate + final
    cudaStreamWaitEvent(0, evJoin, 0);
    aggregate_kernel<<<(n_nodes + 7) / 8, 256>>>(batch, bias, n_nodes);

    dim3 fg(NOUT / 256, GG / 8);
    final_gemm_kernel<<<fg, 256>>>(fc1_w, fc1_b, out);
}